// round 10
// baseline (speedup 1.0000x reference)
#include <cuda_runtime.h>
#include <cstdint>

// out[i,m,l] = w1[i,0]*t4[i,(m-1)%56,l] + w1[i,1]*t4[i,(m-2)%56,l]
// t4 as GEMM over input channels j (K=64 per conv tap; tap = A row shift):
//   D[r, i] += Xsel[p = r + tap][j] * w2[i][3j+tap]
// D rows 0..55 -> t4[na] (l=r), 64..119 -> t4[nb] (l=r-64).
// Single-pass TF32 mma.sync m16n8k8. Grid (56), 512 threads (16 warps).
// Warp owns m-tile PAIR (mt, mt+4) -> same thread holds D[l] and D[64+l]:
// the w1 mix is done in registers, no epilogue staging, one __syncthreads.

static constexpr int A_W     = 68;      // words/row; frag bank = (4g+q)%32, conflict-free
static constexpr int A_ROWS  = 132;
static constexpr int OFF_B_W = A_ROWS * A_W;          // 8976
static constexpr int B_ROWS  = 192;                   // 3 taps x 64 channels
static constexpr int SMEM_TOTAL = (OFF_B_W + B_ROWS * A_W) * 4;   // 88128 B

__device__ __forceinline__ uint32_t f2tf32(float v) {
    uint32_t r; asm("cvt.rna.tf32.f32 %0, %1;" : "=r"(r) : "f"(v)); return r;
}
__device__ __forceinline__ void mma_tf32(float* d, const uint32_t* a, const uint32_t* b) {
    asm("mma.sync.aligned.m16n8k8.row.col.f32.tf32.tf32.f32 "
        "{%0,%1,%2,%3}, {%4,%5,%6,%7}, {%8,%9}, {%0,%1,%2,%3};"
        : "+f"(d[0]), "+f"(d[1]), "+f"(d[2]), "+f"(d[3])
        : "r"(a[0]), "r"(a[1]), "r"(a[2]), "r"(a[3]), "r"(b[0]), "r"(b[1]));
}

__global__ __launch_bounds__(512, 1) void tf32_kernel(
    const float* __restrict__ x,
    const float* __restrict__ w1,
    const float* __restrict__ w2,
    float* __restrict__ out) {

    extern __shared__ uint32_t smem[];
    uint32_t* A = smem;                  // [132][68]: A[p][j]  (tf32 bits)
    uint32_t* B = smem + OFF_B_W;        // [192][68]: B[tap*64+i][j]

    const int tid  = threadIdx.x;
    const int wid  = tid >> 5;
    const int lane = tid & 31;

    const int m  = blockIdx.x;
    const int na = (m + 55) % 56;
    const int nb = (m + 54) % 56;

    // Zero halo rows {0, 57, 64, 121} (272 words, one shot).
    if (tid < 272) {
        int r = tid / 68, w = tid - r * 68;
        int row = (r == 0) ? 0 : (r == 1) ? 57 : (r == 2) ? 64 : 121;
        A[row * A_W + w] = 0u;
    }

    // Fill A: item = (sel, jg, l); 4 j-consecutive channels -> one STS.128.
#pragma unroll
    for (int it = 0; it < 4; ++it) {
        int idx = it * 512 + tid;              // 0..2047, valid <1792
        if (idx < 1792) {
            int sel = idx >= 896;
            int rem = idx - sel * 896;
            int jg  = rem / 56;
            int l   = rem - jg * 56;
            int n   = sel ? nb : na;
            int p   = sel * 64 + 1 + l;
            const float* xp = &x[(jg * 4) * 3136 + n * 56 + l];
            uint4 v;
            v.x = f2tf32(xp[0]);
            v.y = f2tf32(xp[3136]);
            v.z = f2tf32(xp[2 * 3136]);
            v.w = f2tf32(xp[3 * 3136]);
            *reinterpret_cast<uint4*>(&A[p * A_W + jg * 4]) = v;
        }
    }

    // Fill B from float4 loads of w2: B[tap*64+i][j] = tf32(w2[i][3j+tap]).
#pragma unroll
    for (int it = 0; it < 6; ++it) {
        int idx = it * 512 + tid;              // 0..3071 (64 ch * 48 float4)
        int i   = idx / 48;
        int f4  = idx - i * 48;
        float4 v = *reinterpret_cast<const float4*>(&w2[i * 192 + f4 * 4]);
        float vv[4] = {v.x, v.y, v.z, v.w};
#pragma unroll
        for (int e = 0; e < 4; ++e) {
            int jk  = f4 * 4 + e;
            int j   = jk / 3;
            int tap = jk - 3 * j;
            B[(tap * 64 + i) * A_W + j] = f2tf32(vv[e]);
        }
    }

    // Preload w1 for this thread's 4 channels while smem fills drain.
    const int g    = lane >> 2;            // 0..7
    const int q    = lane & 3;             // 0..3
    const int mt0  = wid & 3;              // m-tile pair (mt0, mt0+4)
    const int nb0  = (wid >> 2) * 16;      // n base (2 n-tiles of 8)
    float w1r[4][2];
#pragma unroll
    for (int ntl = 0; ntl < 2; ++ntl)
#pragma unroll
        for (int e = 0; e < 2; ++e) {
            int c = nb0 + ntl * 8 + 2 * q + e;
            w1r[ntl * 2 + e][0] = __ldg(&w1[2 * c]);
            w1r[ntl * 2 + e][1] = __ldg(&w1[2 * c + 1]);
        }

    __syncthreads();

    // ---- Mainloop: 3 taps x 8 k-steps; h=0 -> rows l, h=1 -> rows 64+l ----
    float d[2][2][4];
#pragma unroll
    for (int h = 0; h < 2; ++h)
#pragma unroll
        for (int b = 0; b < 2; ++b)
#pragma unroll
            for (int c = 0; c < 4; ++c) d[h][b][c] = 0.0f;

#pragma unroll
    for (int tap = 0; tap < 3; ++tap) {
#pragma unroll
        for (int ks = 0; ks < 8; ++ks) {
            const int kc = ks * 8 + q;
            uint32_t afr[2][4], bfr[2][2];
#pragma unroll
            for (int h = 0; h < 2; ++h) {
                const int r0 = (mt0 + 4 * h) * 16 + g + tap;
                const uint32_t* p = &A[r0 * A_W + kc];
                afr[h][0] = p[0];
                afr[h][1] = p[8 * A_W];
                afr[h][2] = p[4];
                afr[h][3] = p[8 * A_W + 4];
            }
#pragma unroll
            for (int ntl = 0; ntl < 2; ++ntl) {
                const uint32_t* p = &B[(tap * 64 + nb0 + ntl * 8 + g) * A_W + kc];
                bfr[ntl][0] = p[0];
                bfr[ntl][1] = p[4];
            }
#pragma unroll
            for (int h = 0; h < 2; ++h)
#pragma unroll
                for (int ntl = 0; ntl < 2; ++ntl)
                    mma_tf32(d[h][ntl], afr[h], bfr[ntl]);
        }
    }

    // ---- Register epilogue: out[c, m, l] = w1[c,0]*D[l][c] + w1[c,1]*D[64+l][c]
    const int l1 = mt0 * 16 + g;           // always < 56
    const int l2 = l1 + 8;                 // invalid for mt0 == 3
#pragma unroll
    for (int ntl = 0; ntl < 2; ++ntl) {
#pragma unroll
        for (int e = 0; e < 2; ++e) {
            const int c = nb0 + ntl * 8 + 2 * q + e;
            const float w10 = w1r[ntl * 2 + e][0];
            const float w11 = w1r[ntl * 2 + e][1];
            float* orow = &out[(c * 56 + m) * 56];
            orow[l1] = fmaf(w10, d[0][ntl][e], w11 * d[1][ntl][e]);
            if (l2 < 56)
                orow[l2] = fmaf(w10, d[0][ntl][2 + e], w11 * d[1][ntl][2 + e]);
        }
    }
}

extern "C" void kernel_launch(void* const* d_in, const int* in_sizes, int n_in,
                              void* d_out, int out_size) {
    const float* x  = (const float*)d_in[0];   // (1,64,56,56)
    const float* w1 = (const float*)d_in[1];   // (64,2)
    const float* w2 = (const float*)d_in[2];   // (64,64,3)
    float* out = (float*)d_out;                // (1,64,56,56)

    cudaFuncSetAttribute(tf32_kernel,
                         cudaFuncAttributeMaxDynamicSharedMemorySize, SMEM_TOTAL);

    tf32_kernel<<<56, 512, SMEM_TOTAL>>>(x, w1, w2, out);
}

// round 11
// speedup vs baseline: 1.2043x; 1.2043x over previous
#include <cuda_runtime.h>
#include <cstdint>

// out[i,m,l] = w1[i,0]*t4[i,(m-1)%56,l] + w1[i,1]*t4[i,(m-2)%56,l]
// t4 as GEMM over input channels j (K=64 per conv tap; tap = A row shift):
//   D[r, i'] += Xsel[p = r + tap][j] * w2[ibase+i'][3j+tap]
// D rows 0..55 -> t4[na] (l=r), 64..119 -> t4[nb] (l=r-64).
// Single-pass TF32 mma.sync m16n8k8. Grid (ihalf=2, m=56) = 112 blocks
// (one per SM, single wave), 512 threads (16 warps).
// Warp = m-tile PAIR (mt0, mt0+4) x ONE 8-col n-tile -> 48 MMAs/warp and the
// w1 shift-mix happens in registers (same thread holds D[l] and D[64+l]).

static constexpr int A_W     = 68;      // words/row; frag bank = (4g+q)%32, conflict-free
static constexpr int A_ROWS  = 132;
static constexpr int OFF_B_W = A_ROWS * A_W;          // 8976
static constexpr int B_ROWS  = 96;                    // 3 taps x 32 channels
static constexpr int SMEM_TOTAL = (OFF_B_W + B_ROWS * A_W) * 4;   // 62016 B

__device__ __forceinline__ uint32_t f2tf32(float v) {
    uint32_t r; asm("cvt.rna.tf32.f32 %0, %1;" : "=r"(r) : "f"(v)); return r;
}
__device__ __forceinline__ void mma_tf32(float* d, const uint32_t* a, const uint32_t* b) {
    asm("mma.sync.aligned.m16n8k8.row.col.f32.tf32.tf32.f32 "
        "{%0,%1,%2,%3}, {%4,%5,%6,%7}, {%8,%9}, {%0,%1,%2,%3};"
        : "+f"(d[0]), "+f"(d[1]), "+f"(d[2]), "+f"(d[3])
        : "r"(a[0]), "r"(a[1]), "r"(a[2]), "r"(a[3]), "r"(b[0]), "r"(b[1]));
}

__global__ __launch_bounds__(512, 1) void tf32_kernel(
    const float* __restrict__ x,
    const float* __restrict__ w1,
    const float* __restrict__ w2,
    float* __restrict__ out) {

    extern __shared__ uint32_t smem[];
    uint32_t* A = smem;                  // [132][68]: A[p][j]  (tf32 bits)
    uint32_t* B = smem + OFF_B_W;        // [96][68]:  B[tap*32+i'][j]

    const int tid  = threadIdx.x;
    const int wid  = tid >> 5;
    const int lane = tid & 31;

    const int m     = blockIdx.y;
    const int ihalf = blockIdx.x;
    const int ibase = ihalf * 32;
    const int na    = (m + 55) % 56;
    const int nb    = (m + 54) % 56;

    // Zero halo rows {0, 57, 64, 121} (272 words).
    if (tid < 272) {
        int r = tid / 68, w = tid - r * 68;
        int row = (r == 0) ? 0 : (r == 1) ? 57 : (r == 2) ? 64 : 121;
        A[row * A_W + w] = 0u;
    }

    // Fill A: item = (sel, jg, l); 4 j-consecutive channels -> one STS.128.
#pragma unroll
    for (int it = 0; it < 4; ++it) {
        int idx = it * 512 + tid;              // valid < 1792
        if (idx < 1792) {
            int sel = idx >= 896;
            int rem = idx - sel * 896;
            int jg  = rem / 56;
            int l   = rem - jg * 56;
            int n   = sel ? nb : na;
            int p   = sel * 64 + 1 + l;
            const float* xp = &x[(jg * 4) * 3136 + n * 56 + l];
            uint4 v;
            v.x = f2tf32(xp[0]);
            v.y = f2tf32(xp[3136]);
            v.z = f2tf32(xp[2 * 3136]);
            v.w = f2tf32(xp[3 * 3136]);
            *reinterpret_cast<uint4*>(&A[p * A_W + jg * 4]) = v;
        }
    }

    // Fill B (this half's 32 channels) from float4 loads of w2.
#pragma unroll
    for (int it = 0; it < 3; ++it) {
        int idx = it * 512 + tid;              // 0..1535 (32 ch * 48 float4)
        int i   = idx / 48;
        int f4  = idx - i * 48;
        float4 v = *reinterpret_cast<const float4*>(&w2[(ibase + i) * 192 + f4 * 4]);
        float vv[4] = {v.x, v.y, v.z, v.w};
#pragma unroll
        for (int e = 0; e < 4; ++e) {
            int jk  = f4 * 4 + e;
            int j   = jk / 3;
            int tap = jk - 3 * j;
            B[(tap * 32 + i) * A_W + j] = f2tf32(vv[e]);
        }
    }

    // Warp layout: mt0 = m-tile pair, nt = single 8-col n-tile.
    const int g    = lane >> 2;            // 0..7
    const int q    = lane & 3;             // 0..3
    const int mt0  = wid & 3;              // m-tiles (mt0, mt0+4)
    const int nt   = wid >> 2;             // 0..3 -> cols nt*8 .. nt*8+7

    // Preload w1 for this thread's 2 output channels while smem fills drain.
    float w1r[2][2];
#pragma unroll
    for (int e = 0; e < 2; ++e) {
        int c = ibase + nt * 8 + 2 * q + e;
        w1r[e][0] = __ldg(&w1[2 * c]);
        w1r[e][1] = __ldg(&w1[2 * c + 1]);
    }

    __syncthreads();

    // ---- Mainloop: 3 taps x 8 k-steps x 2 MMAs (h = na/nb row block) ----
    float d[2][4];
#pragma unroll
    for (int h = 0; h < 2; ++h)
#pragma unroll
        for (int c = 0; c < 4; ++c) d[h][c] = 0.0f;

#pragma unroll
    for (int tap = 0; tap < 3; ++tap) {
#pragma unroll
        for (int ks = 0; ks < 8; ++ks) {
            const int kc = ks * 8 + q;
            uint32_t afr[2][4], bfr[2];
#pragma unroll
            for (int h = 0; h < 2; ++h) {
                const int r0 = (mt0 + 4 * h) * 16 + g + tap;
                const uint32_t* p = &A[r0 * A_W + kc];
                afr[h][0] = p[0];
                afr[h][1] = p[8 * A_W];
                afr[h][2] = p[4];
                afr[h][3] = p[8 * A_W + 4];
            }
            {
                const uint32_t* p = &B[(tap * 32 + nt * 8 + g) * A_W + kc];
                bfr[0] = p[0];
                bfr[1] = p[4];
            }
#pragma unroll
            for (int h = 0; h < 2; ++h)
                mma_tf32(d[h], afr[h], bfr);
        }
    }

    // ---- Register epilogue ----
    const int l1 = mt0 * 16 + g;           // < 56 always
    const int l2 = l1 + 8;                 // invalid when mt0 == 3
#pragma unroll
    for (int e = 0; e < 2; ++e) {
        const int c = ibase + nt * 8 + 2 * q + e;
        float* orow = &out[(c * 56 + m) * 56];
        orow[l1] = fmaf(w1r[e][0], d[0][e], w1r[e][1] * d[1][e]);
        if (l2 < 56)
            orow[l2] = fmaf(w1r[e][0], d[0][2 + e], w1r[e][1] * d[1][2 + e]);
    }
}

extern "C" void kernel_launch(void* const* d_in, const int* in_sizes, int n_in,
                              void* d_out, int out_size) {
    const float* x  = (const float*)d_in[0];   // (1,64,56,56)
    const float* w1 = (const float*)d_in[1];   // (64,2)
    const float* w2 = (const float*)d_in[2];   // (64,64,3)
    float* out = (float*)d_out;                // (1,64,56,56)

    cudaFuncSetAttribute(tf32_kernel,
                         cudaFuncAttributeMaxDynamicSharedMemorySize, SMEM_TOTAL);

    dim3 grid(2, 56);
    tf32_kernel<<<grid, 512, SMEM_TOTAL>>>(x, w1, w2, out);
}